// round 8
// baseline (speedup 1.0000x reference)
#include <cuda_runtime.h>
#include <math.h>

#define W_IMG 512
#define H_IMG 512
#define MAX_N (32 * W_IMG * H_IMG)
#define MAX_WORDS (MAX_N / 64)

struct __align__(8) Node { int label; int area; };
__device__ Node g_node[MAX_N];
__device__ float g_inv[MAX_N];                    // 1/(sqrt(area)+1) at run starts
__device__ unsigned long long g_bits[MAX_WORDS];  // fg bitmask, 64 px/word
// 0 = sum_fg bce/(w+1), 1 = sum_bg bce, 2 = sum_fg w (=Σ_roots a^1.5), 3 = N_fg
__device__ double g_acc[4];

// ---------------------------------------------------------------------------
__device__ __forceinline__ int find_root(int x) {
    int p = g_node[x].label;
    while (p != x) { x = p; p = g_node[x].label; }
    return p;
}

__device__ __forceinline__ void merge(int a, int b) {
    bool done = false;
    do {
        a = find_root(a);
        b = find_root(b);
        if (a < b) { int t = a; a = b; b = t; }
        if (a != b) {
            int old = atomicMin(&g_node[a].label, b);
            done = (old == a);
            a = old;
        } else {
            done = true;
        }
    } while (!done);
}

__device__ __forceinline__ int rs_in_word(unsigned long long m, int k) {
    unsigned long long below = (k == 0) ? 0ull : ((1ull << k) - 1ull);
    unsigned long long z = (~m) & below;
    return z ? (64 - __clzll(z)) : 0;
}

__device__ __forceinline__ int run_len(unsigned long long m, int k) {
    unsigned long long inv = ~(m >> k);
    return inv ? (__ffsll((long long)inv) - 1) : (64 - k);
}

__device__ __forceinline__ double warp_sum(double v) {
#pragma unroll
    for (int off = 16; off > 0; off >>= 1)
        v += __shfl_down_sync(0xFFFFFFFFu, v, off);
    return v;
}

// ---------------------------------------------------------------------------
// k_prep: thread per quad; build word mask via shfl; init nodes at owned
// run starts (single 8B store).
// ---------------------------------------------------------------------------
__global__ void k_prep(const float* __restrict__ tgt, int nquad) {
    int t = blockIdx.x * blockDim.x + threadIdx.x;
    if (t < nquad) {
        int w = t >> 4;
        int b0 = (t & 15) << 2;
        float4 v = __ldg(&((const float4*)tgt)[t]);
        unsigned long long nib = 0ull;
        if (v.x > 0.f) nib |= 1ull;
        if (v.y > 0.f) nib |= 2ull;
        if (v.z > 0.f) nib |= 4ull;
        if (v.w > 0.f) nib |= 8ull;
        unsigned long long m = nib << b0;
        m |= __shfl_xor_sync(0xFFFFFFFFu, m, 1);
        m |= __shfl_xor_sync(0xFFFFFFFFu, m, 2);
        m |= __shfl_xor_sync(0xFFFFFFFFu, m, 4);
        m |= __shfl_xor_sync(0xFFFFFFFFu, m, 8);
        if ((t & 15) == 0) g_bits[w] = m;

        unsigned int s = (unsigned int)(((m & ~(m << 1)) >> b0) & 0xFull);
        int base = (w << 6) + b0;
        while (s) {
            int k = __ffs(s) - 1;
            s &= s - 1;
            int node = base + k;
            *(int2*)&g_node[node] = make_int2(node, 0);
        }
    }
    if (blockIdx.x == 0 && threadIdx.x < 4) g_acc[threadIdx.x] = 0.0;
}

// ---------------------------------------------------------------------------
// k_union: word-level bitmask merges
// ---------------------------------------------------------------------------
__global__ void k_union(int nwords) {
    int w = blockIdx.x * blockDim.x + threadIdx.x;
    if (w >= nwords) return;
    unsigned long long cur = g_bits[w];
    if (!cur) return;
    int base = w << 6;
    int wx = w & 7;
    int wy = (w >> 3) & (H_IMG - 1);

    if (wx && (cur & 1ull)) {
        unsigned long long L = g_bits[w - 1];
        if (L >> 63) merge(base, ((w - 1) << 6) + rs_in_word(L, 63));
    }
    if (wy) {
        unsigned long long up = g_bits[w - 8];
        unsigned long long ov = cur & up;
        unsigned long long need = ov & ~(ov << 1);
        while (need) {
            int k = __ffsll((long long)need) - 1;
            need &= need - 1;
            merge(base + rs_in_word(cur, k),
                  ((w - 8) << 6) + rs_in_word(up, k));
        }
    }
}

// ---------------------------------------------------------------------------
// k_area: thread per quad; owned run starts -> compress + area accumulate
// ---------------------------------------------------------------------------
__global__ void k_area(int nquad) {
    int t = blockIdx.x * blockDim.x + threadIdx.x;
    if (t >= nquad) return;
    int w = t >> 4;
    int b0 = (t & 15) << 2;
    unsigned long long m = __ldg(&g_bits[w]);
    unsigned int s = (unsigned int)(((m & ~(m << 1)) >> b0) & 0xFull);
    if (!s) return;
    int base = w << 6;
    while (s) {
        int k = __ffs(s) - 1;
        s &= s - 1;
        int kk = b0 + k;
        int node = base + kk;
        int root = find_root(node);
        if (root != node) g_node[node].label = root;   // compress
        atomicAdd(&g_node[root].area, run_len(m, kk));
    }
}

// ---------------------------------------------------------------------------
// k_wgt: per owned run-start -> store inv=1/(sqrt(area)+1); at roots also
// accumulate Σ area^1.5 (= Σ_fg w) and Σ area (= N_fg).
// ---------------------------------------------------------------------------
__global__ void k_wgt(int nquad) {
    double d2 = 0.0, d3 = 0.0;
    int t = blockIdx.x * blockDim.x + threadIdx.x;
    if (t < nquad) {
        int w = t >> 4;
        int b0 = (t & 15) << 2;
        unsigned long long m = __ldg(&g_bits[w]);
        unsigned int s = (unsigned int)(((m & ~(m << 1)) >> b0) & 0xFull);
        if (s) {
            int base = w << 6;
            float f2 = 0.f, f3 = 0.f;
            while (s) {
                int k = __ffs(s) - 1;
                s &= s - 1;
                int idx = base + b0 + k;
                int2 la = *(const int2*)&g_node[idx];   // {label, area}
                int root = la.x;
                int area = (root == idx) ? la.y : __ldg(&g_node[root].area);
                float fa = (float)area;
                float sq = sqrtf(fa);
                g_inv[idx] = __fdividef(1.f, sq + 1.f);
                if (root == idx) { f2 += fa * sq; f3 += fa; }
            }
            d2 = f2; d3 = f3;
        }
    }
    __shared__ double sh[2][8];
    int lane = threadIdx.x & 31;
    int warp = threadIdx.x >> 5;
    d2 = warp_sum(d2); d3 = warp_sum(d3);
    if (lane == 0) { sh[0][warp] = d2; sh[1][warp] = d3; }
    __syncthreads();
    if (warp == 0) {
        int nw = blockDim.x >> 5;
        double v2 = (lane < nw) ? sh[0][lane] : 0.0;
        double v3 = (lane < nw) ? sh[1][lane] : 0.0;
        v2 = warp_sum(v2); v3 = warp_sum(v3);
        if (lane == 0) {
            atomicAdd(&g_acc[2], v2);
            atomicAdd(&g_acc[3], v3);
        }
    }
}

// ---------------------------------------------------------------------------
// k_bce: 2 quads/thread, front-batched loads; per fg pixel a single
// independent 4B g_inv load (no chained gather).
// ---------------------------------------------------------------------------
__global__ void k_bce(const float* __restrict__ in, int npair) {
    float f0 = 0.f, f1 = 0.f;
    int t = blockIdx.x * blockDim.x + threadIdx.x;
    if (t < npair) {
        const float4* in4 = (const float4*)in;
        int q0 = t * 2;
        int q1 = q0 + 1;
        // front-batched loads
        unsigned long long m0 = __ldg(&g_bits[q0 >> 4]);
        unsigned long long m1 = __ldg(&g_bits[q1 >> 4]);
        float4 v0 = __ldg(&in4[q0]);
        float4 v1 = __ldg(&in4[q1]);

        unsigned long long ms[2] = {m0, m1};
        float4 vs[2] = {v0, v1};
#pragma unroll
        for (int p = 0; p < 2; p++) {
            int q = q0 + p;
            unsigned long long m = ms[p];
            int kk0 = (q & 15) << 2;
            int base = (q >> 4) << 6;
            float xs[4] = {vs[p].x, vs[p].y, vs[p].z, vs[p].w};
#pragma unroll
            for (int l = 0; l < 4; l++) {
                int kk = kk0 + l;
                float x = xs[l];
                float gpl = __logf(1.f + __expf(-fabsf(x)));
                float b = gpl + fmaxf(x, 0.f);        // bce if bg
                if ((m >> kk) & 1ull) {
                    float inv = __ldg(&g_inv[base + rs_in_word(m, kk)]);
                    f0 += (b - x) * inv;              // bce_fg = b - x
                } else {
                    f1 += b;
                }
            }
        }
    }

    double d0 = f0, d1 = f1;
    __shared__ double sh[2][8];
    int lane = threadIdx.x & 31;
    int warp = threadIdx.x >> 5;
    d0 = warp_sum(d0); d1 = warp_sum(d1);
    if (lane == 0) { sh[0][warp] = d0; sh[1][warp] = d1; }
    __syncthreads();
    if (warp == 0) {
        int nw = blockDim.x >> 5;
        double v0 = (lane < nw) ? sh[0][lane] : 0.0;
        double v1 = (lane < nw) ? sh[1][lane] : 0.0;
        v0 = warp_sum(v0); v1 = warp_sum(v1);
        if (lane == 0) {
            atomicAdd(&g_acc[0], v0);
            atomicAdd(&g_acc[1], v1);
        }
    }
}

__global__ void k_final(float* __restrict__ out, double inv_n) {
    double nfg = g_acc[3];
    double mean_nz = g_acc[2] / (nfg > 0.0 ? nfg : 1.0);
    double loss = (g_acc[0] + g_acc[1] / (mean_nz + 1.0)) * inv_n;
    out[0] = (float)loss;
}

// ---------------------------------------------------------------------------
extern "C" void kernel_launch(void* const* d_in, const int* in_sizes, int n_in,
                              void* d_out, int out_size) {
    const float* inputs  = (const float*)d_in[0];
    const float* targets = (const float*)d_in[1];
    float* out = (float*)d_out;

    int n = in_sizes[0];
    int nwords = n >> 6;
    int nquad = n >> 2;
    int npair = n >> 3;
    const int threads = 256;
    int qblocks = (nquad + threads - 1) / threads;
    int wblocks = (nwords + threads - 1) / threads;
    int pblocks = (npair + threads - 1) / threads;

    k_prep<<<qblocks, threads>>>(targets, nquad);
    k_union<<<wblocks, threads>>>(nwords);
    k_area<<<qblocks, threads>>>(nquad);
    k_wgt<<<qblocks, threads>>>(nquad);
    k_bce<<<pblocks, threads>>>(inputs, npair);
    k_final<<<1, 1>>>(out, 1.0 / (double)n);
}

// round 9
// speedup vs baseline: 1.1921x; 1.1921x over previous
#include <cuda_runtime.h>
#include <math.h>

#define W_IMG 512
#define H_IMG 512
#define MAX_N (32 * W_IMG * H_IMG)
#define MAX_WORDS (MAX_N / 64)
#define MAX_NODES (MAX_WORDS * 32)   // <=32 runs per 64-px word

// Run-indexed node arrays: 16.8 MB each -> L2-resident.
__device__ int g_lab[MAX_NODES];    // UF parent; after k_wgt: float inv bits
__device__ int g_ar[MAX_NODES];     // per-root area
__device__ unsigned long long g_bits[MAX_WORDS];
// 0 = sum_fg bce/(w+1), 1 = sum_bg bce, 2 = sum_fg w (=Σ_roots a^1.5), 3 = N_fg
__device__ double g_acc[4];

// ---------------------------------------------------------------------------
__device__ __forceinline__ int find_root(int x) {
    int p = g_lab[x];
    while (p != x) { x = p; p = g_lab[x]; }
    return p;
}

__device__ __forceinline__ void merge(int a, int b) {
    bool done = false;
    do {
        a = find_root(a);
        b = find_root(b);
        if (a < b) { int t = a; a = b; b = t; }
        if (a != b) {
            int old = atomicMin(&g_lab[a], b);
            done = (old == a);
            a = old;
        } else {
            done = true;
        }
    } while (!done);
}

// node id of the run CONTAINING set bit k of word w with starts mask st
__device__ __forceinline__ int node_of(int w, unsigned long long st, int k) {
    return (w << 5) + __popcll(st & ((2ull << k) - 1ull)) - 1;
}
// node id of the run STARTING at bit k
__device__ __forceinline__ int node_at(int w, unsigned long long st, int k) {
    return (w << 5) + __popcll(st & ((1ull << k) - 1ull));
}

__device__ __forceinline__ int run_len(unsigned long long m, int k) {
    unsigned long long inv = ~(m >> k);
    return inv ? (__ffsll((long long)inv) - 1) : (64 - k);
}

__device__ __forceinline__ double warp_sum(double v) {
#pragma unroll
    for (int off = 16; off > 0; off >>= 1)
        v += __shfl_down_sync(0xFFFFFFFFu, v, off);
    return v;
}

// ---------------------------------------------------------------------------
// k_prep: thread per quad; build word mask via shfl; init nodes at owned
// run starts (run-indexed -> one 128B line per word).
// ---------------------------------------------------------------------------
__global__ void k_prep(const float* __restrict__ tgt, int nquad) {
    int t = blockIdx.x * blockDim.x + threadIdx.x;
    if (t < nquad) {
        int w = t >> 4;
        int b0 = (t & 15) << 2;
        float4 v = __ldg(&((const float4*)tgt)[t]);
        unsigned long long nib = 0ull;
        if (v.x > 0.f) nib |= 1ull;
        if (v.y > 0.f) nib |= 2ull;
        if (v.z > 0.f) nib |= 4ull;
        if (v.w > 0.f) nib |= 8ull;
        unsigned long long m = nib << b0;
        m |= __shfl_xor_sync(0xFFFFFFFFu, m, 1);
        m |= __shfl_xor_sync(0xFFFFFFFFu, m, 2);
        m |= __shfl_xor_sync(0xFFFFFFFFu, m, 4);
        m |= __shfl_xor_sync(0xFFFFFFFFu, m, 8);
        if ((t & 15) == 0) g_bits[w] = m;

        unsigned long long st = m & ~(m << 1);
        unsigned int s = (unsigned int)((st >> b0) & 0xFull);
        while (s) {
            int k = __ffs(s) - 1;
            s &= s - 1;
            int id = node_at(w, st, b0 + k);
            g_lab[id] = id;
            g_ar[id] = 0;
        }
    }
    if (blockIdx.x == 0 && threadIdx.x < 4) g_acc[threadIdx.x] = 0.0;
}

// ---------------------------------------------------------------------------
// k_union: word-level bitmask merges (run-indexed node ids)
// ---------------------------------------------------------------------------
__global__ void k_union(int nwords) {
    int w = blockIdx.x * blockDim.x + threadIdx.x;
    if (w >= nwords) return;
    unsigned long long cur = g_bits[w];
    if (!cur) return;
    unsigned long long stc = cur & ~(cur << 1);
    int wx = w & 7;
    int wy = (w >> 3) & (H_IMG - 1);

    if (wx && (cur & 1ull)) {
        unsigned long long L = g_bits[w - 1];
        if (L >> 63) {
            unsigned long long stl = L & ~(L << 1);
            merge((w << 5), ((w - 1) << 5) + __popcll(stl) - 1);
        }
    }
    if (wy) {
        unsigned long long up = g_bits[w - 8];
        unsigned long long ov = cur & up;
        if (ov) {
            unsigned long long stu = up & ~(up << 1);
            unsigned long long need = ov & ~(ov << 1);
            while (need) {
                int k = __ffsll((long long)need) - 1;
                need &= need - 1;
                merge(node_of(w, stc, k), node_of(w - 8, stu, k));
            }
        }
    }
}

// ---------------------------------------------------------------------------
// k_area: thread per quad; owned run starts -> compress + area accumulate
// ---------------------------------------------------------------------------
__global__ void k_area(int nquad) {
    int t = blockIdx.x * blockDim.x + threadIdx.x;
    if (t >= nquad) return;
    int w = t >> 4;
    int b0 = (t & 15) << 2;
    unsigned long long m = __ldg(&g_bits[w]);
    unsigned long long st = m & ~(m << 1);
    unsigned int s = (unsigned int)((st >> b0) & 0xFull);
    if (!s) return;
    while (s) {
        int k = __ffs(s) - 1;
        s &= s - 1;
        int kk = b0 + k;
        int node = node_at(w, st, kk);
        int root = find_root(node);
        if (root != node) g_lab[node] = root;    // compress
        atomicAdd(&g_ar[root], run_len(m, kk));
    }
}

// ---------------------------------------------------------------------------
// k_wgt: per owned run-start -> overwrite label slot with inv=1/(sqrt(a)+1);
// at roots accumulate Σ a^1.5 (= Σ_fg w) and Σ a (= N_fg).
// Safe: each label slot is read only by its owner before overwrite;
// non-roots read only the root's AREA slot.
// ---------------------------------------------------------------------------
__global__ void k_wgt(int nquad) {
    double d2 = 0.0, d3 = 0.0;
    int t = blockIdx.x * blockDim.x + threadIdx.x;
    if (t < nquad) {
        int w = t >> 4;
        int b0 = (t & 15) << 2;
        unsigned long long m = __ldg(&g_bits[w]);
        unsigned long long st = m & ~(m << 1);
        unsigned int s = (unsigned int)((st >> b0) & 0xFull);
        if (s) {
            float f2 = 0.f, f3 = 0.f;
            while (s) {
                int k = __ffs(s) - 1;
                s &= s - 1;
                int idx = node_at(w, st, b0 + k);
                int root = g_lab[idx];              // compressed in k_area
                int area = (root == idx) ? g_ar[idx] : __ldg(&g_ar[root]);
                float fa = (float)area;
                float sq = sqrtf(fa);
                g_lab[idx] = __float_as_int(__fdividef(1.f, sq + 1.f));
                if (root == idx) { f2 += fa * sq; f3 += fa; }
            }
            d2 = f2; d3 = f3;
        }
    }
    __shared__ double sh[2][8];
    int lane = threadIdx.x & 31;
    int warp = threadIdx.x >> 5;
    d2 = warp_sum(d2); d3 = warp_sum(d3);
    if (lane == 0) { sh[0][warp] = d2; sh[1][warp] = d3; }
    __syncthreads();
    if (warp == 0) {
        int nw = blockDim.x >> 5;
        double v2 = (lane < nw) ? sh[0][lane] : 0.0;
        double v3 = (lane < nw) ? sh[1][lane] : 0.0;
        v2 = warp_sum(v2); v3 = warp_sum(v3);
        if (lane == 0) {
            atomicAdd(&g_acc[2], v2);
            atomicAdd(&g_acc[3], v3);
        }
    }
}

// ---------------------------------------------------------------------------
// k_bce: 2 quads/thread, front-batched loads; per fg pixel ONE independent
// 4B L2-resident inv load (no chain, no run-carry).
// ---------------------------------------------------------------------------
__global__ void k_bce(const float* __restrict__ in, int npair) {
    float f0 = 0.f, f1 = 0.f;
    int t = blockIdx.x * blockDim.x + threadIdx.x;
    if (t < npair) {
        const float4* in4 = (const float4*)in;
        int q0 = t * 2;
        unsigned long long m0 = __ldg(&g_bits[q0 >> 4]);
        unsigned long long m1 = __ldg(&g_bits[(q0 + 1) >> 4]);
        float4 v0 = __ldg(&in4[q0]);
        float4 v1 = __ldg(&in4[q0 + 1]);

        unsigned long long ms[2] = {m0, m1};
        float4 vs[2] = {v0, v1};
#pragma unroll
        for (int p = 0; p < 2; p++) {
            int q = q0 + p;
            unsigned long long m = ms[p];
            unsigned long long st = m & ~(m << 1);
            int w = q >> 4;
            int kk0 = (q & 15) << 2;
            float xs[4] = {vs[p].x, vs[p].y, vs[p].z, vs[p].w};
#pragma unroll
            for (int l = 0; l < 4; l++) {
                int kk = kk0 + l;
                float x = xs[l];
                float gpl = __logf(1.f + __expf(-fabsf(x)));
                float b = gpl + fmaxf(x, 0.f);        // bce if bg
                if ((m >> kk) & 1ull) {
                    float inv = __int_as_float(__ldg(&g_lab[node_of(w, st, kk)]));
                    f0 += (b - x) * inv;              // bce_fg = b - x
                } else {
                    f1 += b;
                }
            }
        }
    }

    double d0 = f0, d1 = f1;
    __shared__ double sh[2][8];
    int lane = threadIdx.x & 31;
    int warp = threadIdx.x >> 5;
    d0 = warp_sum(d0); d1 = warp_sum(d1);
    if (lane == 0) { sh[0][warp] = d0; sh[1][warp] = d1; }
    __syncthreads();
    if (warp == 0) {
        int nw = blockDim.x >> 5;
        double v0 = (lane < nw) ? sh[0][lane] : 0.0;
        double v1 = (lane < nw) ? sh[1][lane] : 0.0;
        v0 = warp_sum(v0); v1 = warp_sum(v1);
        if (lane == 0) {
            atomicAdd(&g_acc[0], v0);
            atomicAdd(&g_acc[1], v1);
        }
    }
}

__global__ void k_final(float* __restrict__ out, double inv_n) {
    double nfg = g_acc[3];
    double mean_nz = g_acc[2] / (nfg > 0.0 ? nfg : 1.0);
    double loss = (g_acc[0] + g_acc[1] / (mean_nz + 1.0)) * inv_n;
    out[0] = (float)loss;
}

// ---------------------------------------------------------------------------
extern "C" void kernel_launch(void* const* d_in, const int* in_sizes, int n_in,
                              void* d_out, int out_size) {
    const float* inputs  = (const float*)d_in[0];
    const float* targets = (const float*)d_in[1];
    float* out = (float*)d_out;

    int n = in_sizes[0];
    int nwords = n >> 6;
    int nquad = n >> 2;
    int npair = n >> 3;
    const int threads = 256;
    int qblocks = (nquad + threads - 1) / threads;
    int wblocks = (nwords + threads - 1) / threads;
    int pblocks = (npair + threads - 1) / threads;

    k_prep<<<qblocks, threads>>>(targets, nquad);
    k_union<<<wblocks, threads>>>(nwords);
    k_area<<<qblocks, threads>>>(nquad);
    k_wgt<<<qblocks, threads>>>(nquad);
    k_bce<<<pblocks, threads>>>(inputs, npair);
    k_final<<<1, 1>>>(out, 1.0 / (double)n);
}

// round 10
// speedup vs baseline: 1.4292x; 1.1989x over previous
#include <cuda_runtime.h>
#include <math.h>

#define W_IMG 512
#define H_IMG 512
#define MAX_N (32 * W_IMG * H_IMG)
#define MAX_WORDS (MAX_N / 64)
#define MAX_NODES (MAX_WORDS * 32)   // <=32 runs per 64-px word

// Run-indexed node arrays: 16.8 MB each -> L2-resident.
__device__ int g_lab[MAX_NODES];    // UF parent (compressed to root by k_area)
__device__ int g_ar[MAX_NODES];     // area: seeded with own run length by k_prep
__device__ unsigned long long g_bits[MAX_WORDS];
// 0 = sum_fg bce/(w+1), 1 = sum_bg bce, 2 = sum_fg w, 3 = N_fg
__device__ double g_acc[4];

// ---------------------------------------------------------------------------
__device__ __forceinline__ int find_root(int x) {
    int p = g_lab[x];
    while (p != x) { x = p; p = g_lab[x]; }
    return p;
}

__device__ __forceinline__ void merge(int a, int b) {
    bool done = false;
    do {
        a = find_root(a);
        b = find_root(b);
        if (a < b) { int t = a; a = b; b = t; }
        if (a != b) {
            int old = atomicMin(&g_lab[a], b);
            done = (old == a);
            a = old;
        } else {
            done = true;
        }
    } while (!done);
}

// node id of the run CONTAINING set bit k of word w with starts mask st
__device__ __forceinline__ int node_of(int w, unsigned long long st, int k) {
    return (w << 5) + __popcll(st & ((2ull << k) - 1ull)) - 1;
}
// node id of the run STARTING at bit k
__device__ __forceinline__ int node_at(int w, unsigned long long st, int k) {
    return (w << 5) + __popcll(st & ((1ull << k) - 1ull));
}

__device__ __forceinline__ int run_len(unsigned long long m, int k) {
    unsigned long long inv = ~(m >> k);
    return inv ? (__ffsll((long long)inv) - 1) : (64 - k);
}

__device__ __forceinline__ double warp_sum(double v) {
#pragma unroll
    for (int off = 16; off > 0; off >>= 1)
        v += __shfl_down_sync(0xFFFFFFFFu, v, off);
    return v;
}

// ---------------------------------------------------------------------------
// k_prep: thread per quad; build word mask via shfl; init nodes at owned
// run starts. Area seeded with own run length (k_area then only adds
// non-root contributions).
// ---------------------------------------------------------------------------
__global__ void k_prep(const float* __restrict__ tgt, int nquad) {
    int t = blockIdx.x * blockDim.x + threadIdx.x;
    if (t < nquad) {
        int w = t >> 4;
        int b0 = (t & 15) << 2;
        float4 v = __ldg(&((const float4*)tgt)[t]);
        unsigned long long nib = 0ull;
        if (v.x > 0.f) nib |= 1ull;
        if (v.y > 0.f) nib |= 2ull;
        if (v.z > 0.f) nib |= 4ull;
        if (v.w > 0.f) nib |= 8ull;
        unsigned long long m = nib << b0;
        m |= __shfl_xor_sync(0xFFFFFFFFu, m, 1);
        m |= __shfl_xor_sync(0xFFFFFFFFu, m, 2);
        m |= __shfl_xor_sync(0xFFFFFFFFu, m, 4);
        m |= __shfl_xor_sync(0xFFFFFFFFu, m, 8);
        if ((t & 15) == 0) g_bits[w] = m;

        unsigned long long st = m & ~(m << 1);
        unsigned int s = (unsigned int)((st >> b0) & 0xFull);
        while (s) {
            int k = __ffs(s) - 1;
            s &= s - 1;
            int kk = b0 + k;
            int id = node_at(w, st, kk);
            g_lab[id] = id;
            g_ar[id] = run_len(m, kk);      // seed with own run length
        }
    }
    if (blockIdx.x == 0 && threadIdx.x < 4) g_acc[threadIdx.x] = 0.0;
}

// ---------------------------------------------------------------------------
// k_union: word-level bitmask merges (run-indexed node ids)
// ---------------------------------------------------------------------------
__global__ void k_union(int nwords) {
    int w = blockIdx.x * blockDim.x + threadIdx.x;
    if (w >= nwords) return;
    unsigned long long cur = g_bits[w];
    if (!cur) return;
    unsigned long long stc = cur & ~(cur << 1);
    int wx = w & 7;
    int wy = (w >> 3) & (H_IMG - 1);

    if (wx && (cur & 1ull)) {
        unsigned long long L = g_bits[w - 1];
        if (L >> 63) {
            unsigned long long stl = L & ~(L << 1);
            merge((w << 5), ((w - 1) << 5) + __popcll(stl) - 1);
        }
    }
    if (wy) {
        unsigned long long up = g_bits[w - 8];
        unsigned long long ov = cur & up;
        if (ov) {
            unsigned long long stu = up & ~(up << 1);
            unsigned long long need = ov & ~(ov << 1);
            while (need) {
                int k = __ffsll((long long)need) - 1;
                need &= need - 1;
                merge(node_of(w, stc, k), node_of(w - 8, stu, k));
            }
        }
    }
}

// ---------------------------------------------------------------------------
// k_area: thread per quad; owned run starts -> compress + add own length
// to root (only for non-root nodes; roots were seeded in k_prep).
// ---------------------------------------------------------------------------
__global__ void k_area(int nquad) {
    int t = blockIdx.x * blockDim.x + threadIdx.x;
    if (t >= nquad) return;
    int w = t >> 4;
    int b0 = (t & 15) << 2;
    unsigned long long m = __ldg(&g_bits[w]);
    unsigned long long st = m & ~(m << 1);
    unsigned int s = (unsigned int)((st >> b0) & 0xFull);
    if (!s) return;
    while (s) {
        int k = __ffs(s) - 1;
        s &= s - 1;
        int kk = b0 + k;
        int node = node_at(w, st, kk);
        int root = find_root(node);
        if (root != node) {
            g_lab[node] = root;                      // compress
            atomicAdd(&g_ar[root], run_len(m, kk));  // add own length
        }
    }
}

// ---------------------------------------------------------------------------
// k_bce: 2 quads/thread, front-batched loads; per fg pixel a 2-hop lookup
// (lab -> ar), both L2-resident; f2/f3 accumulated per-pixel.
// ---------------------------------------------------------------------------
__global__ void k_bce(const float* __restrict__ in, int npair) {
    float f0 = 0.f, f1 = 0.f, f2 = 0.f, f3 = 0.f;
    int t = blockIdx.x * blockDim.x + threadIdx.x;
    if (t < npair) {
        const float4* in4 = (const float4*)in;
        int q0 = t * 2;
        unsigned long long m0 = __ldg(&g_bits[q0 >> 4]);
        unsigned long long m1 = __ldg(&g_bits[(q0 + 1) >> 4]);
        float4 v0 = __ldg(&in4[q0]);
        float4 v1 = __ldg(&in4[q0 + 1]);

        unsigned long long ms[2] = {m0, m1};
        float4 vs[2] = {v0, v1};
#pragma unroll
        for (int p = 0; p < 2; p++) {
            int q = q0 + p;
            unsigned long long m = ms[p];
            unsigned long long st = m & ~(m << 1);
            int w = q >> 4;
            int kk0 = (q & 15) << 2;
            float xs[4] = {vs[p].x, vs[p].y, vs[p].z, vs[p].w};
#pragma unroll
            for (int l = 0; l < 4; l++) {
                int kk = kk0 + l;
                float x = xs[l];
                float gpl = __logf(1.f + __expf(-fabsf(x)));
                float b = gpl + fmaxf(x, 0.f);        // bce if bg
                if ((m >> kk) & 1ull) {
                    int node = node_of(w, st, kk);
                    int root = __ldg(&g_lab[node]);   // compressed root
                    float a = (float)__ldg(&g_ar[root]);
                    float wgt = sqrtf(a);
                    f0 += __fdividef(b - x, wgt + 1.f);  // bce_fg = b - x
                    f2 += wgt;
                    f3 += 1.f;
                } else {
                    f1 += b;
                }
            }
        }
    }

    double d0 = f0, d1 = f1, d2 = f2, d3 = f3;
    __shared__ double sh[4][8];
    int lane = threadIdx.x & 31;
    int warp = threadIdx.x >> 5;
    d0 = warp_sum(d0); d1 = warp_sum(d1); d2 = warp_sum(d2); d3 = warp_sum(d3);
    if (lane == 0) { sh[0][warp] = d0; sh[1][warp] = d1; sh[2][warp] = d2; sh[3][warp] = d3; }
    __syncthreads();
    int nw = blockDim.x >> 5;
    if (warp == 0) {
        double v0 = (lane < nw) ? sh[0][lane] : 0.0;
        double v1 = (lane < nw) ? sh[1][lane] : 0.0;
        double v2 = (lane < nw) ? sh[2][lane] : 0.0;
        double v3 = (lane < nw) ? sh[3][lane] : 0.0;
        v0 = warp_sum(v0); v1 = warp_sum(v1); v2 = warp_sum(v2); v3 = warp_sum(v3);
        if (lane == 0) {
            atomicAdd(&g_acc[0], v0);
            atomicAdd(&g_acc[1], v1);
            atomicAdd(&g_acc[2], v2);
            atomicAdd(&g_acc[3], v3);
        }
    }
}

__global__ void k_final(float* __restrict__ out, double inv_n) {
    double nfg = g_acc[3];
    double mean_nz = g_acc[2] / (nfg > 0.0 ? nfg : 1.0);
    double loss = (g_acc[0] + g_acc[1] / (mean_nz + 1.0)) * inv_n;
    out[0] = (float)loss;
}

// ---------------------------------------------------------------------------
extern "C" void kernel_launch(void* const* d_in, const int* in_sizes, int n_in,
                              void* d_out, int out_size) {
    const float* inputs  = (const float*)d_in[0];
    const float* targets = (const float*)d_in[1];
    float* out = (float*)d_out;

    int n = in_sizes[0];
    int nwords = n >> 6;
    int nquad = n >> 2;
    int npair = n >> 3;
    const int threads = 256;
    int qblocks = (nquad + threads - 1) / threads;
    int wblocks = (nwords + threads - 1) / threads;
    int pblocks = (npair + threads - 1) / threads;

    k_prep<<<qblocks, threads>>>(targets, nquad);
    k_union<<<wblocks, threads>>>(nwords);
    k_area<<<qblocks, threads>>>(nquad);
    k_bce<<<pblocks, threads>>>(inputs, npair);
    k_final<<<1, 1>>>(out, 1.0 / (double)n);
}

// round 11
// speedup vs baseline: 1.4415x; 1.0086x over previous
#include <cuda_runtime.h>
#include <math.h>

#define W_IMG 512
#define H_IMG 512
#define MAX_N (32 * W_IMG * H_IMG)
#define MAX_WORDS (MAX_N / 64)
#define MAX_NODES (MAX_WORDS * 32)   // <=32 runs per 64-px word

// Run-indexed node arrays: 16.8 MB each -> L2-resident.
__device__ int g_lab[MAX_NODES];    // UF parent (compressed to root by k_area)
__device__ int g_ar[MAX_NODES];     // area: seeded with own run length by k_prep
__device__ unsigned long long g_bits[MAX_WORDS];
// 0 = sum_fg bce/(w+1), 1 = sum_bg bce, 2 = sum_fg w, 3 = N_fg
__device__ double g_acc[4];

// ---------------------------------------------------------------------------
__device__ __forceinline__ int find_root(int x) {
    int p = g_lab[x];
    while (p != x) { x = p; p = g_lab[x]; }
    return p;
}

__device__ __forceinline__ void merge(int a, int b) {
    bool done = false;
    do {
        a = find_root(a);
        b = find_root(b);
        if (a < b) { int t = a; a = b; b = t; }
        if (a != b) {
            int old = atomicMin(&g_lab[a], b);
            done = (old == a);
            a = old;
        } else {
            done = true;
        }
    } while (!done);
}

// node id of the run CONTAINING set bit k of word w with starts mask st
__device__ __forceinline__ int node_of(int w, unsigned long long st, int k) {
    return (w << 5) + __popcll(st & ((2ull << k) - 1ull)) - 1;
}
// node id of the run STARTING at bit k
__device__ __forceinline__ int node_at(int w, unsigned long long st, int k) {
    return (w << 5) + __popcll(st & ((1ull << k) - 1ull));
}

__device__ __forceinline__ int run_len(unsigned long long m, int k) {
    unsigned long long inv = ~(m >> k);
    return inv ? (__ffsll((long long)inv) - 1) : (64 - k);
}

__device__ __forceinline__ double warp_sum(double v) {
#pragma unroll
    for (int off = 16; off > 0; off >>= 1)
        v += __shfl_down_sync(0xFFFFFFFFu, v, off);
    return v;
}

// ---------------------------------------------------------------------------
// k_prep: thread per quad; build word mask via shfl; init nodes at owned
// run starts. Area seeded with own run length.
// ---------------------------------------------------------------------------
__global__ void k_prep(const float* __restrict__ tgt, int nquad) {
    int t = blockIdx.x * blockDim.x + threadIdx.x;
    if (t < nquad) {
        int w = t >> 4;
        int b0 = (t & 15) << 2;
        float4 v = __ldg(&((const float4*)tgt)[t]);
        unsigned long long nib = 0ull;
        if (v.x > 0.f) nib |= 1ull;
        if (v.y > 0.f) nib |= 2ull;
        if (v.z > 0.f) nib |= 4ull;
        if (v.w > 0.f) nib |= 8ull;
        unsigned long long m = nib << b0;
        m |= __shfl_xor_sync(0xFFFFFFFFu, m, 1);
        m |= __shfl_xor_sync(0xFFFFFFFFu, m, 2);
        m |= __shfl_xor_sync(0xFFFFFFFFu, m, 4);
        m |= __shfl_xor_sync(0xFFFFFFFFu, m, 8);
        if ((t & 15) == 0) g_bits[w] = m;

        unsigned long long st = m & ~(m << 1);
        unsigned int s = (unsigned int)((st >> b0) & 0xFull);
        while (s) {
            int k = __ffs(s) - 1;
            s &= s - 1;
            int kk = b0 + k;
            int id = node_at(w, st, kk);
            g_lab[id] = id;
            g_ar[id] = run_len(m, kk);      // seed with own run length
        }
    }
    if (blockIdx.x == 0 && threadIdx.x < 4) g_acc[threadIdx.x] = 0.0;
}

// ---------------------------------------------------------------------------
// k_union: word-level bitmask merges (run-indexed node ids)
// ---------------------------------------------------------------------------
__global__ void k_union(int nwords) {
    int w = blockIdx.x * blockDim.x + threadIdx.x;
    if (w >= nwords) return;
    unsigned long long cur = g_bits[w];
    if (!cur) return;
    unsigned long long stc = cur & ~(cur << 1);
    int wx = w & 7;
    int wy = (w >> 3) & (H_IMG - 1);

    if (wx && (cur & 1ull)) {
        unsigned long long L = g_bits[w - 1];
        if (L >> 63) {
            unsigned long long stl = L & ~(L << 1);
            merge((w << 5), ((w - 1) << 5) + __popcll(stl) - 1);
        }
    }
    if (wy) {
        unsigned long long up = g_bits[w - 8];
        unsigned long long ov = cur & up;
        if (ov) {
            unsigned long long stu = up & ~(up << 1);
            unsigned long long need = ov & ~(ov << 1);
            while (need) {
                int k = __ffsll((long long)need) - 1;
                need &= need - 1;
                merge(node_of(w, stc, k), node_of(w - 8, stu, k));
            }
        }
    }
}

// ---------------------------------------------------------------------------
// k_area: thread per quad; owned run starts -> compress + add own length
// to root (only for non-root nodes; roots were seeded in k_prep).
// ---------------------------------------------------------------------------
__global__ void k_area(int nquad) {
    int t = blockIdx.x * blockDim.x + threadIdx.x;
    if (t >= nquad) return;
    int w = t >> 4;
    int b0 = (t & 15) << 2;
    unsigned long long m = __ldg(&g_bits[w]);
    unsigned long long st = m & ~(m << 1);
    unsigned int s = (unsigned int)((st >> b0) & 0xFull);
    if (!s) return;
    while (s) {
        int k = __ffs(s) - 1;
        s &= s - 1;
        int kk = b0 + k;
        int node = node_at(w, st, kk);
        int root = find_root(node);
        if (root != node) {
            g_lab[node] = root;                      // compress
            atomicAdd(&g_ar[root], run_len(m, kk));  // add own length
        }
    }
}

// ---------------------------------------------------------------------------
// k_bce: thread per 8 px (one word segment). FULLY BRANCHLESS:
// all 8 node ids computed up-front (bg clamped to 0 -> valid, discarded),
// 8 independent lab loads, then 8 independent ar loads, select-based math.
// ---------------------------------------------------------------------------
__global__ void k_bce(const float* __restrict__ in, int npair) {
    float f0 = 0.f, f1 = 0.f, f2 = 0.f, f3 = 0.f;
    int t = blockIdx.x * blockDim.x + threadIdx.x;
    if (t < npair) {
        const float4* in4 = (const float4*)in;
        int q0 = t * 2;
        int w = q0 >> 4;                 // both quads in same 64-px word
        int kk0 = (q0 & 15) << 2;        // 0,8,16,...,56

        unsigned long long m = __ldg(&g_bits[w]);
        float4 v0 = __ldg(&in4[q0]);
        float4 v1 = __ldg(&in4[q0 + 1]);

        unsigned long long st = m & ~(m << 1);
        unsigned int fgb = (unsigned int)((m >> kk0) & 0xFFull);
        int wbase = w << 5;

        // batch 1: 8 independent node ids + lab loads
        int root[8];
#pragma unroll
        for (int l = 0; l < 8; l++) {
            int kk = kk0 + l;
            int nid = wbase + __popcll(st & ((2ull << kk) - 1ull)) - 1;
            nid = max(nid, 0);
            root[l] = __ldg(&g_lab[nid]);
        }
        // batch 2: 8 independent area loads
        float a[8];
#pragma unroll
        for (int l = 0; l < 8; l++)
            a[l] = (float)__ldg(&g_ar[root[l]]);

        float xs[8] = {v0.x, v0.y, v0.z, v0.w, v1.x, v1.y, v1.z, v1.w};
#pragma unroll
        for (int l = 0; l < 8; l++) {
            float x = xs[l];
            float gpl = __logf(1.f + __expf(-fabsf(x)));
            float b = gpl + fmaxf(x, 0.f);            // bce if bg
            float wgt = sqrtf(a[l]);
            float invw = __fdividef(1.f, wgt + 1.f);
            float sel = (float)((fgb >> l) & 1u);     // 1 if fg
            f0 += sel * (b - x) * invw;               // bce_fg = b - x
            f1 += b - sel * b;
            f2 += sel * wgt;
            f3 += sel;
        }
    }

    double d0 = f0, d1 = f1, d2 = f2, d3 = f3;
    __shared__ double sh[4][8];
    int lane = threadIdx.x & 31;
    int warp = threadIdx.x >> 5;
    d0 = warp_sum(d0); d1 = warp_sum(d1); d2 = warp_sum(d2); d3 = warp_sum(d3);
    if (lane == 0) { sh[0][warp] = d0; sh[1][warp] = d1; sh[2][warp] = d2; sh[3][warp] = d3; }
    __syncthreads();
    int nw = blockDim.x >> 5;
    if (warp == 0) {
        double v0 = (lane < nw) ? sh[0][lane] : 0.0;
        double v1 = (lane < nw) ? sh[1][lane] : 0.0;
        double v2 = (lane < nw) ? sh[2][lane] : 0.0;
        double v3 = (lane < nw) ? sh[3][lane] : 0.0;
        v0 = warp_sum(v0); v1 = warp_sum(v1); v2 = warp_sum(v2); v3 = warp_sum(v3);
        if (lane == 0) {
            atomicAdd(&g_acc[0], v0);
            atomicAdd(&g_acc[1], v1);
            atomicAdd(&g_acc[2], v2);
            atomicAdd(&g_acc[3], v3);
        }
    }
}

__global__ void k_final(float* __restrict__ out, double inv_n) {
    double nfg = g_acc[3];
    double mean_nz = g_acc[2] / (nfg > 0.0 ? nfg : 1.0);
    double loss = (g_acc[0] + g_acc[1] / (mean_nz + 1.0)) * inv_n;
    out[0] = (float)loss;
}

// ---------------------------------------------------------------------------
extern "C" void kernel_launch(void* const* d_in, const int* in_sizes, int n_in,
                              void* d_out, int out_size) {
    const float* inputs  = (const float*)d_in[0];
    const float* targets = (const float*)d_in[1];
    float* out = (float*)d_out;

    int n = in_sizes[0];
    int nwords = n >> 6;
    int nquad = n >> 2;
    int npair = n >> 3;
    const int threads = 256;
    int qblocks = (nquad + threads - 1) / threads;
    int wblocks = (nwords + threads - 1) / threads;
    int pblocks = (npair + threads - 1) / threads;

    k_prep<<<qblocks, threads>>>(targets, nquad);
    k_union<<<wblocks, threads>>>(nwords);
    k_area<<<qblocks, threads>>>(nquad);
    k_bce<<<pblocks, threads>>>(inputs, npair);
    k_final<<<1, 1>>>(out, 1.0 / (double)n);
}